// round 13
// baseline (speedup 1.0000x reference)
#include <cuda_runtime.h>
#include <cstdint>
#include <cstddef>

#define N_NODES 100000
#define N_EDGES 1600000
#define F_IN 92
#define E_IN 50
#define D 64
#define N_LAYERS 3
#define N_GRAPHS 512
#define BN_EPS 1e-5f

typedef unsigned long long u64;
typedef long long i64;

// ---------------- scratch (device globals; no runtime allocation) ----------------
// g_kqv layout per node (192 floats):
//   [0..63]   : k' = h@Wk + bk + bq                (used at dst)
//   [64..191] : interleaved qv: for col pair c (0..31):
//               [64+4c+0,1] = q[2c], q[2c+1]       (used at src)
//               [64+4c+2,3] = v[2c], v[2c+1] (+bv) (used at src)
__device__ float g_h[N_NODES * D];
__device__ float g_kqv[N_NODES * 3 * D];
__device__ float g_agg[N_NODES * D];        // init = h@Wskip + conv_bias, edges atomically add
__device__ float g_stats[2 * D];            // BN col sums / sumsq
__device__ float g_gsum[N_GRAPHS * D];      // pooling sums
__device__ float g_gcnt[N_GRAPHS];          // pooling counts
__device__ int2  g_sd[N_EDGES];             // packed (src,dst) int32 indices
__device__ int   g_bidx[N_NODES];

// ---------------- packed f32x2 helpers ----------------
__device__ __forceinline__ u64 pack2(float x, float y) {
    u64 r; asm("mov.b64 %0,{%1,%2};" : "=l"(r) : "f"(x), "f"(y)); return r;
}
__device__ __forceinline__ u64 dup2(float x) {
    u64 r; asm("mov.b64 %0,{%1,%1};" : "=l"(r) : "f"(x)); return r;
}
__device__ __forceinline__ float2 unpk(u64 v) {
    float2 o; asm("mov.b64 {%0,%1},%2;" : "=f"(o.x), "=f"(o.y) : "l"(v)); return o;
}
__device__ __forceinline__ u64 ffma2(u64 a, u64 b, u64 c) {
    u64 d; asm("fma.rn.f32x2 %0,%1,%2,%3;" : "=l"(d) : "l"(a), "l"(b), "l"(c)); return d;
}
__device__ __forceinline__ u64 addf2(u64 a, u64 b) {
    u64 d; asm("add.rn.f32x2 %0,%1,%2;" : "=l"(d) : "l"(a), "l"(b)); return d;
}
__device__ __forceinline__ float silu_f(float x) {
    return __fdividef(x, 1.0f + __expf(-x));
}
__device__ __forceinline__ void pf_l1(const void* p) {
    asm volatile("prefetch.global.L1 [%0];" :: "l"(p));
}

// ---------------- index normalize (dtype self-detect; no separate launch) ----------------
// If edge_index is int64 (nonneg < 2^31), every odd 32-bit word of its first 128B is 0.
__global__ __launch_bounds__(256) void k_convert(const void* __restrict__ eidx,
                                                 const void* __restrict__ bidx) {
    __shared__ int s64;
    if (threadIdx.x == 0) {
        const unsigned* w = (const unsigned*)eidx;
        int is64 = 1;
        for (int i = 1; i < 129; i += 2)
            if (w[i] != 0u) { is64 = 0; break; }
        s64 = is64;
    }
    __syncthreads();
    const int is64 = s64;
    int gt = blockIdx.x * 256 + threadIdx.x;
    int stride = gridDim.x * 256;
    if (is64) {
        const i64* e = (const i64*)eidx;
        const i64* b = (const i64*)bidx;
        for (int i = gt; i < N_EDGES; i += stride)
            g_sd[i] = make_int2((int)e[i], (int)e[N_EDGES + i]);
        for (int i = gt; i < N_NODES; i += stride) g_bidx[i] = (int)b[i];
    } else {
        const int* e = (const int*)eidx;
        const int* b = (const int*)bidx;
        for (int i = gt; i < N_EDGES; i += stride)
            g_sd[i] = make_int2(e[i], e[N_EDGES + i]);
        for (int i = gt; i < N_NODES; i += stride) g_bidx[i] = b[i];
    }
}

// ---------------- pre-FC: h = silu(x @ pre_w + pre_b) ----------------
__global__ __launch_bounds__(256) void k_prefc(const float* __restrict__ x,
                                               const float* __restrict__ w,
                                               const float* __restrict__ b) {
    __shared__ float ws[F_IN * D];       // 23552 B
    __shared__ float xs[64 * F_IN];      // 23552 B
    int t = threadIdx.x;
    for (int i = t; i < F_IN * D; i += 256) ws[i] = w[i];
    int nb = blockIdx.x * 64;
    for (int i = t; i < 64 * F_IN; i += 256) {
        int r = i / F_IN, c = i - r * F_IN;
        int node = nb + r;
        xs[i] = (node < N_NODES) ? x[(size_t)node * F_IN + c] : 0.f;
    }
    __syncthreads();
    int cg = t & 15;
    int r0 = t >> 4;
    float4 bb = *(const float4*)&b[4 * cg];
    for (int pass = 0; pass < 4; ++pass) {
        int row = pass * 16 + r0;
        int node = nb + row;
        u64 a0 = 0ull, a1 = 0ull;
#pragma unroll 4
        for (int j = 0; j < F_IN; ++j) {
            u64 xv = dup2(xs[row * F_IN + j]);
            float4 wv = *(const float4*)&ws[j * D + 4 * cg];
            a0 = ffma2(xv, pack2(wv.x, wv.y), a0);
            a1 = ffma2(xv, pack2(wv.z, wv.w), a1);
        }
        if (node < N_NODES) {
            float2 p0 = unpk(a0), p1 = unpk(a1);
            float4 o;
            o.x = silu_f(p0.x + bb.x);
            o.y = silu_f(p0.y + bb.y);
            o.z = silu_f(p1.x + bb.z);
            o.w = silu_f(p1.y + bb.w);
            *(float4*)&g_h[node * D + 4 * cg] = o;
        }
    }
}

// ---------------- node GEMM: [k'|qv-interleaved] -> g_kqv, skip+conv_bias -> g_agg -----
#define HP 130
__global__ __launch_bounds__(256, 2) void k_nodegemm(
    const float* __restrict__ Wk, const float* __restrict__ bk,
    const float* __restrict__ Wq, const float* __restrict__ bq,
    const float* __restrict__ Wv, const float* __restrict__ bv,
    const float* __restrict__ Wskip, const float* __restrict__ cbias, int l) {
    extern __shared__ float dsm[];
    float* wsm = dsm;               // [64][256]
    float* hst = dsm + 64 * 256;    // [64][HP] transposed h tile
    int t = threadIdx.x;
    const float* WK = Wk + l * D * D;
    const float* WQ = Wq + l * D * D;
    const float* WV = Wv + l * D * D;
    const float* WS = Wskip + l * D * D;
    const float* BK = bk + l * D;
    const float* BQ = bq + l * D;
    const float* BV = bv + l * D;
    const float* CB = cbias + l * D;

    for (int i = t; i < 64 * 256; i += 256) {
        int j = i >> 8, c = i & 255;
        float v;
        if (c < 64)       v = WK[j * 64 + c];
        else if (c < 128) v = WQ[j * 64 + c - 64];
        else if (c < 192) v = WV[j * 64 + c - 128];
        else              v = WS[j * 64 + c - 192];
        wsm[i] = v;
    }
    int nb = blockIdx.x * 128;
    for (int i = t; i < 128 * 64; i += 256) {
        int r = i >> 6, c = i & 63;
        int node = nb + r;
        hst[c * HP + r] = (node < N_NODES) ? g_h[node * D + c] : 0.f;
    }
    if (blockIdx.x == 0 && t < 2 * D) g_stats[t] = 0.f;  // zero BN stats for this layer
    __syncthreads();

    int cg = t & 31;
    int warp = t >> 5;
    int cA = 4 * cg;          // 0..124
    int cB = 128 + 4 * cg;    // 128..252
    float4 bA, bB;
    if (cA < 64) bA = make_float4(BK[cA] + BQ[cA], BK[cA + 1] + BQ[cA + 1],
                                  BK[cA + 2] + BQ[cA + 2], BK[cA + 3] + BQ[cA + 3]);
    else         bA = make_float4(0.f, 0.f, 0.f, 0.f);
    if (cB < 192) bB = make_float4(BV[cB - 128], BV[cB - 127], BV[cB - 126], BV[cB - 125]);
    else          bB = make_float4(CB[cB - 192], CB[cB - 191], CB[cB - 190], CB[cB - 189]);

    for (int pass = 0; pass < 2; ++pass) {
        int rowbase = pass * 64 + warp * 8;
        u64 accA[4][4], accB[4][4];   // [rowpair][col]
#pragma unroll
        for (int pp = 0; pp < 4; ++pp)
#pragma unroll
            for (int cc = 0; cc < 4; ++cc) { accA[pp][cc] = 0ull; accB[pp][cc] = 0ull; }
#pragma unroll 8
        for (int j = 0; j < 64; ++j) {
            float4 wA = *(const float4*)&wsm[j * 256 + cA];
            float4 wB = *(const float4*)&wsm[j * 256 + cB];
            u64 wa0 = dup2(wA.x), wa1 = dup2(wA.y), wa2 = dup2(wA.z), wa3 = dup2(wA.w);
            u64 wb0 = dup2(wB.x), wb1 = dup2(wB.y), wb2 = dup2(wB.z), wb3 = dup2(wB.w);
            const float* hj = &hst[j * HP + rowbase];
#pragma unroll
            for (int pp = 0; pp < 4; ++pp) {
                u64 h2 = *(const u64*)&hj[2 * pp];   // broadcast LDS.64 (rows 2pp,2pp+1)
                accA[pp][0] = ffma2(h2, wa0, accA[pp][0]);
                accA[pp][1] = ffma2(h2, wa1, accA[pp][1]);
                accA[pp][2] = ffma2(h2, wa2, accA[pp][2]);
                accA[pp][3] = ffma2(h2, wa3, accA[pp][3]);
                accB[pp][0] = ffma2(h2, wb0, accB[pp][0]);
                accB[pp][1] = ffma2(h2, wb1, accB[pp][1]);
                accB[pp][2] = ffma2(h2, wb2, accB[pp][2]);
                accB[pp][3] = ffma2(h2, wb3, accB[pp][3]);
            }
        }
#pragma unroll
        for (int pp = 0; pp < 4; ++pp) {
            float2 uA[4], uB[4];
#pragma unroll
            for (int cc = 0; cc < 4; ++cc) { uA[cc] = unpk(accA[pp][cc]); uB[cc] = unpk(accB[pp][cc]); }
#pragma unroll
            for (int s = 0; s < 2; ++s) {
                int node = nb + rowbase + 2 * pp + s;
                if (node >= N_NODES) continue;
                float a0 = (s ? uA[0].y : uA[0].x) + bA.x;
                float a1 = (s ? uA[1].y : uA[1].x) + bA.y;
                float a2 = (s ? uA[2].y : uA[2].x) + bA.z;
                float a3 = (s ? uA[3].y : uA[3].x) + bA.w;
                float b0 = (s ? uB[0].y : uB[0].x) + bB.x;
                float b1 = (s ? uB[1].y : uB[1].x) + bB.y;
                float b2 = (s ? uB[2].y : uB[2].x) + bB.z;
                float b3 = (s ? uB[3].y : uB[3].x) + bB.w;
                if (cA < 64) {
                    *(float4*)&g_kqv[node * 192 + cA] = make_float4(a0, a1, a2, a3);
                } else {
                    int q0 = cA - 64;   // multiple of 4
                    *(float2*)&g_kqv[node * 192 + 64 + 2 * q0]     = make_float2(a0, a1);
                    *(float2*)&g_kqv[node * 192 + 64 + 2 * q0 + 4] = make_float2(a2, a3);
                }
                if (cB < 192) {
                    int v0 = cB - 128;  // multiple of 4
                    *(float2*)&g_kqv[node * 192 + 64 + 2 * v0 + 2] = make_float2(b0, b1);
                    *(float2*)&g_kqv[node * 192 + 64 + 2 * v0 + 6] = make_float2(b2, b3);
                } else {
                    *(float4*)&g_agg[node * 64 + (cB - 192)] = make_float4(b0, b1, b2, b3);
                }
            }
        }
    }
}

// ---------------- edge kernel: NO smem. attr via uniform broadcast LDG (L1-resident,
// prefetch 2 edges ahead); kv via direct LDG regs (depth-1); We in 100 regs. ----------
__global__ __launch_bounds__(128, 3) void k_edge(const float* __restrict__ eattr,
                                                 const float* __restrict__ We, int l) {
    const int lane = threadIdx.x & 31;
    const float* WE = We + l * E_IN * D;
    u64 wr[E_IN];
#pragma unroll
    for (int j = 0; j < E_IN; ++j) {
        float2 v = *(const float2*)&WE[j * D + 2 * lane];
        wr[j] = pack2(v.x, v.y);
    }
    const int gw = (blockIdx.x * blockDim.x + threadIdx.x) >> 5;
    const int nw = (gridDim.x * blockDim.x) >> 5;
#define CL(x) ((x) < N_EDGES ? (x) : (N_EDGES - 1))
    int e = gw;
    if (e >= N_EDGES) return;
    int2 pC = g_sd[e];
    int2 pN = g_sd[CL(e + nw)];
    // prime L1 with attr rows for edges e and e+nw (rows are 200B -> up to 3 lines)
    {
        const char* r0 = (const char*)(eattr + (size_t)e * E_IN);
        const char* r1 = (const char*)(eattr + (size_t)CL(e + nw) * E_IN);
        pf_l1(r0); pf_l1(r0 + 100); pf_l1(r0 + 199);
        pf_l1(r1); pf_l1(r1 + 100); pf_l1(r1 + 199);
    }
    // current kv (direct gather into regs)
    float2 kC = *(const float2*)&g_kqv[pC.y * 192 + 2 * lane];
    float4 qvC = *(const float4*)&g_kqv[pC.x * 192 + 64 + 4 * lane];

    while (e < N_EDGES) {
        // depth-2: indices + attr-line prefetch for e+2nw
        int2 pNN = g_sd[CL(e + 2 * nw)];
        {
            const char* r2 = (const char*)(eattr + (size_t)CL(e + 2 * nw) * E_IN);
            pf_l1(r2); pf_l1(r2 + 100); pf_l1(r2 + 199);
        }
        // depth-1: kv gather for e+nw
        float2 kN = *(const float2*)&g_kqv[pN.y * 192 + 2 * lane];
        float4 qvN = *(const float4*)&g_kqv[pN.x * 192 + 64 + 4 * lane];
        // ---- e = attr @ We via uniform (warp-broadcast) loads from L1 ----
        // rows are only 8B-aligned (200B stride): pick the 16B-aligned float4
        // phase by edge parity (warp-uniform branch).
        const float* row = eattr + (size_t)e * E_IN;
        u64 a0 = 0ull, a1 = 0ull;
        if (e & 1) {
            float2 t = *(const float2*)row;
            a0 = ffma2(dup2(t.x), wr[0], a0);
            a1 = ffma2(dup2(t.y), wr[1], a1);
#pragma unroll
            for (int jc = 0; jc < 12; ++jc) {
                float4 a = *(const float4*)(row + 2 + 4 * jc);
                a0 = ffma2(dup2(a.x), wr[2 + 4 * jc],     a0);
                a1 = ffma2(dup2(a.y), wr[2 + 4 * jc + 1], a1);
                a0 = ffma2(dup2(a.z), wr[2 + 4 * jc + 2], a0);
                a1 = ffma2(dup2(a.w), wr[2 + 4 * jc + 3], a1);
            }
        } else {
#pragma unroll
            for (int jc = 0; jc < 12; ++jc) {
                float4 a = *(const float4*)(row + 4 * jc);
                a0 = ffma2(dup2(a.x), wr[4 * jc],     a0);
                a1 = ffma2(dup2(a.y), wr[4 * jc + 1], a1);
                a0 = ffma2(dup2(a.z), wr[4 * jc + 2], a0);
                a1 = ffma2(dup2(a.w), wr[4 * jc + 3], a1);
            }
            float2 t = *(const float2*)(row + 48);
            a0 = ffma2(dup2(t.x), wr[48], a0);
            a1 = ffma2(dup2(t.y), wr[49], a1);
        }
        float2 ev = unpk(addf2(a0, a1));
        // ---- gate + scatter ----
        float x0 = kC.x + qvC.x + 2.0f * ev.x;   // k' includes bk+bq
        float x1 = kC.y + qvC.y + 2.0f * ev.y;
        float2 m;
        m.x = silu_f(x0) * (qvC.z + ev.x);
        m.y = silu_f(x1) * (qvC.w + ev.y);
        atomicAdd((float2*)&g_agg[pC.y * 64 + 2 * lane], m);
        // rotate pipeline
        kC = kN; qvC = qvN; pC = pN; pN = pNN;
        e += nw;
    }
#undef CL
}

// ---------------- BN stats: per-column sum & sumsq over nodes ----------------
__global__ __launch_bounds__(256) void k_bnstats() {
    int t = threadIdx.x;
    int col = t & 63;
    int rs = t >> 6;
    float s = 0.f, s2 = 0.f;
    for (int row = blockIdx.x * 4 + rs; row < N_NODES; row += gridDim.x * 4) {
        float v = g_agg[row * 64 + col];
        s += v; s2 += v * v;
    }
    __shared__ float sh[256], sh2[256];
    sh[t] = s; sh2[t] = s2;
    __syncthreads();
    if (rs == 0) {
        s = sh[col] + sh[col + 64] + sh[col + 128] + sh[col + 192];
        s2 = sh2[col] + sh2[col + 64] + sh2[col + 128] + sh2[col + 192];
        atomicAdd(&g_stats[col], s);
        atomicAdd(&g_stats[64 + col], s2);
    }
}

// ---------------- BN apply: h = (agg-mean)*rsqrt(var+eps)*gamma+beta; also zero pool bufs ---
__global__ __launch_bounds__(256) void k_bnapply(const float* __restrict__ gamma,
                                                 const float* __restrict__ beta, int l) {
    __shared__ float sc[64], sf[64];
    int t = threadIdx.x;
    if (t < 64) {
        const float invN = 1.0f / (float)N_NODES;
        float mean = g_stats[t] * invN;
        float var = g_stats[64 + t] * invN - mean * mean;
        float gm = gamma[l * 64 + t], bt = beta[l * 64 + t];
        float scale = gm * rsqrtf(var + BN_EPS);
        sc[t] = scale;
        sf[t] = bt - mean * scale;
    }
    __syncthreads();
    int gt = blockIdx.x * 256 + t;
    int stride = gridDim.x * 256;
    for (int i = gt; i < N_NODES * 64; i += stride) {
        int col = i & 63;
        g_h[i] = g_agg[i] * sc[col] + sf[col];
    }
    for (int i = gt; i < N_GRAPHS * 64; i += stride) g_gsum[i] = 0.f;
    for (int i = gt; i < N_GRAPHS; i += stride) g_gcnt[i] = 0.f;
}

// ---------------- global mean pool (sums + counts via atomics) ----------------
__global__ __launch_bounds__(256) void k_pool() {
    int t = threadIdx.x;
    int col = t & 63;
    int rs = t >> 6;
    for (int row = blockIdx.x * 4 + rs; row < N_NODES; row += gridDim.x * 4) {
        int b = g_bidx[row];
        atomicAdd(&g_gsum[b * 64 + col], g_h[row * 64 + col]);
        if (col == 0) atomicAdd(&g_gcnt[b], 1.f);
    }
}

// ---------------- final: g = silu(mean @ post_w + post_b); out = g @ out_w + out_b ------
__global__ __launch_bounds__(128) void k_final(const float* __restrict__ pw,
                                               const float* __restrict__ pb,
                                               const float* __restrict__ ow,
                                               const float* __restrict__ ob,
                                               float* __restrict__ out) {
    __shared__ float ws[64 * 64];
    __shared__ float sg[4][64];
    int t = threadIdx.x;
    for (int i = t; i < 4096; i += 128) ws[i] = pw[i];
    __syncthreads();
    int lane = t & 31, w = t >> 5;
    int g = blockIdx.x * 4 + w;
    if (g < N_GRAPHS) {
        float inv = 1.0f / fmaxf(g_gcnt[g], 1.0f);
        sg[w][lane] = g_gsum[g * 64 + lane] * inv;
        sg[w][lane + 32] = g_gsum[g * 64 + lane + 32] * inv;
    }
    __syncwarp();
    if (g < N_GRAPHS) {
        float a0 = pb[lane], a1 = pb[lane + 32];
#pragma unroll 8
        for (int j = 0; j < 64; ++j) {
            float xv = sg[w][j];
            a0 = fmaf(xv, ws[j * 64 + lane], a0);
            a1 = fmaf(xv, ws[j * 64 + lane + 32], a1);
        }
        float t0 = silu_f(a0), t1 = silu_f(a1);
        float p = t0 * ow[lane] + t1 * ow[lane + 32];
#pragma unroll
        for (int o = 16; o; o >>= 1) p += __shfl_down_sync(0xffffffffu, p, o);
        if (lane == 0) out[g] = p + ob[0];
    }
}

// ---------------- launch ----------------
extern "C" void kernel_launch(void* const* d_in, const int* in_sizes, int n_in,
                              void* d_out, int out_size) {
    const float* x     = (const float*)d_in[0];
    const void*  eidx  = d_in[1];
    const float* eattr = (const float*)d_in[2];
    const void*  bidx  = d_in[3];
    const float* pre_w = (const float*)d_in[4];
    const float* pre_b = (const float*)d_in[5];
    const float* Wk    = (const float*)d_in[6];
    const float* bk    = (const float*)d_in[7];
    const float* Wq    = (const float*)d_in[8];
    const float* bq    = (const float*)d_in[9];
    const float* Wv    = (const float*)d_in[10];
    const float* bv    = (const float*)d_in[11];
    const float* We    = (const float*)d_in[12];
    const float* Wskip = (const float*)d_in[13];
    const float* cbias = (const float*)d_in[14];
    const float* gamma = (const float*)d_in[15];
    const float* beta  = (const float*)d_in[16];
    const float* pw    = (const float*)d_in[17];
    const float* pb    = (const float*)d_in[18];
    const float* ow    = (const float*)d_in[19];
    const float* ob    = (const float*)d_in[20];
    float* out = (float*)d_out;
    (void)in_sizes; (void)n_in; (void)out_size;

    const int gemm_smem = (64 * 256 + 64 * HP) * (int)sizeof(float);  // 98816 B
    cudaFuncSetAttribute(k_nodegemm, cudaFuncAttributeMaxDynamicSharedMemorySize, gemm_smem);

    // Launch order keeps k_edge in the profiled (4th) slot.
    k_convert<<<256, 256>>>(eidx, bidx);
    k_prefc<<<(N_NODES + 63) / 64, 256>>>(x, pre_w, pre_b);
    for (int l = 0; l < N_LAYERS; ++l) {
        k_nodegemm<<<(N_NODES + 127) / 128, 256, gemm_smem>>>(Wk, bk, Wq, bq, Wv, bv,
                                                              Wskip, cbias, l);
        k_edge<<<444, 128>>>(eattr, We, l);
        k_bnstats<<<128, 256>>>();
        k_bnapply<<<512, 256>>>(gamma, beta, l);
    }
    k_pool<<<256, 256>>>();
    k_final<<<(N_GRAPHS + 3) / 4, 128>>>(pw, pb, ow, ob, out);
}

// round 14
// speedup vs baseline: 1.7176x; 1.7176x over previous
#include <cuda_runtime.h>
#include <cstdint>
#include <cstddef>

#define N_NODES 100000
#define N_EDGES 1600000
#define F_IN 92
#define E_IN 50
#define D 64
#define N_LAYERS 3
#define N_GRAPHS 512
#define BN_EPS 1e-5f

typedef unsigned long long u64;
typedef long long i64;

// ---------------- scratch (device globals; no runtime allocation) ----------------
// g_kqv layout per node (192 floats):
//   [0..63]   : k' = h@Wk + bk + bq                (used at dst)
//   [64..191] : interleaved qv: for col pair c (0..31):
//               [64+4c+0,1] = q[2c], q[2c+1]       (used at src)
//               [64+4c+2,3] = v[2c], v[2c+1] (+bv) (used at src)
__device__ float g_h[N_NODES * D];
__device__ float g_kqv[N_NODES * 3 * D];
__device__ float g_agg[N_NODES * D];        // init = h@Wskip + conv_bias, edges atomically add
__device__ float g_stats[2 * D];            // BN col sums / sumsq
__device__ float g_gsum[N_GRAPHS * D];      // pooling sums
__device__ float g_gcnt[N_GRAPHS];          // pooling counts
__device__ int2  g_sd[N_EDGES];             // packed (src,dst) int32 indices
__device__ int   g_bidx[N_NODES];

// ---------------- packed f32x2 helpers ----------------
__device__ __forceinline__ u64 pack2(float x, float y) {
    u64 r; asm("mov.b64 %0,{%1,%2};" : "=l"(r) : "f"(x), "f"(y)); return r;
}
__device__ __forceinline__ u64 dup2(float x) {
    u64 r; asm("mov.b64 %0,{%1,%1};" : "=l"(r) : "f"(x)); return r;
}
__device__ __forceinline__ float2 unpk(u64 v) {
    float2 o; asm("mov.b64 {%0,%1},%2;" : "=f"(o.x), "=f"(o.y) : "l"(v)); return o;
}
__device__ __forceinline__ u64 ffma2(u64 a, u64 b, u64 c) {
    u64 d; asm("fma.rn.f32x2 %0,%1,%2,%3;" : "=l"(d) : "l"(a), "l"(b), "l"(c)); return d;
}
__device__ __forceinline__ u64 addf2(u64 a, u64 b) {
    u64 d; asm("add.rn.f32x2 %0,%1,%2;" : "=l"(d) : "l"(a), "l"(b)); return d;
}
__device__ __forceinline__ float silu_f(float x) {
    return __fdividef(x, 1.0f + __expf(-x));
}
// cp.async with explicit L2 cache policy (evict_first for streams, evict_last for
// the kqv gather working set) — keeps the 76MB kqv table resident in L2.
__device__ __forceinline__ void cpa8_pol(uint32_t s, const void* g, u64 pol) {
    asm volatile("cp.async.ca.shared.global.L2::cache_hint [%0], [%1], 8, %2;"
                 :: "r"(s), "l"(g), "l"(pol));
}
__device__ __forceinline__ void cpa16_pol(uint32_t s, const void* g, u64 pol) {
    asm volatile("cp.async.ca.shared.global.L2::cache_hint [%0], [%1], 16, %2;"
                 :: "r"(s), "l"(g), "l"(pol));
}

// ---------------- index normalize (dtype self-detect; no separate launch) ----------------
// If edge_index is int64 (nonneg < 2^31), every odd 32-bit word of its first 128B is 0.
__global__ __launch_bounds__(256) void k_convert(const void* __restrict__ eidx,
                                                 const void* __restrict__ bidx) {
    __shared__ int s64;
    if (threadIdx.x == 0) {
        const unsigned* w = (const unsigned*)eidx;
        int is64 = 1;
        for (int i = 1; i < 129; i += 2)
            if (w[i] != 0u) { is64 = 0; break; }
        s64 = is64;
    }
    __syncthreads();
    const int is64 = s64;
    int gt = blockIdx.x * 256 + threadIdx.x;
    int stride = gridDim.x * 256;
    if (is64) {
        const i64* e = (const i64*)eidx;
        const i64* b = (const i64*)bidx;
        for (int i = gt; i < N_EDGES; i += stride)
            g_sd[i] = make_int2((int)e[i], (int)e[N_EDGES + i]);
        for (int i = gt; i < N_NODES; i += stride) g_bidx[i] = (int)b[i];
    } else {
        const int* e = (const int*)eidx;
        const int* b = (const int*)bidx;
        for (int i = gt; i < N_EDGES; i += stride)
            g_sd[i] = make_int2(e[i], e[N_EDGES + i]);
        for (int i = gt; i < N_NODES; i += stride) g_bidx[i] = b[i];
    }
}

// ---------------- pre-FC: h = silu(x @ pre_w + pre_b) ----------------
__global__ __launch_bounds__(256) void k_prefc(const float* __restrict__ x,
                                               const float* __restrict__ w,
                                               const float* __restrict__ b) {
    __shared__ float ws[F_IN * D];       // 23552 B
    __shared__ float xs[64 * F_IN];      // 23552 B
    int t = threadIdx.x;
    for (int i = t; i < F_IN * D; i += 256) ws[i] = w[i];
    int nb = blockIdx.x * 64;
    for (int i = t; i < 64 * F_IN; i += 256) {
        int r = i / F_IN, c = i - r * F_IN;
        int node = nb + r;
        xs[i] = (node < N_NODES) ? x[(size_t)node * F_IN + c] : 0.f;
    }
    __syncthreads();
    int cg = t & 15;
    int r0 = t >> 4;
    float4 bb = *(const float4*)&b[4 * cg];
    for (int pass = 0; pass < 4; ++pass) {
        int row = pass * 16 + r0;
        int node = nb + row;
        u64 a0 = 0ull, a1 = 0ull;
#pragma unroll 4
        for (int j = 0; j < F_IN; ++j) {
            u64 xv = dup2(xs[row * F_IN + j]);
            float4 wv = *(const float4*)&ws[j * D + 4 * cg];
            a0 = ffma2(xv, pack2(wv.x, wv.y), a0);
            a1 = ffma2(xv, pack2(wv.z, wv.w), a1);
        }
        if (node < N_NODES) {
            float2 p0 = unpk(a0), p1 = unpk(a1);
            float4 o;
            o.x = silu_f(p0.x + bb.x);
            o.y = silu_f(p0.y + bb.y);
            o.z = silu_f(p1.x + bb.z);
            o.w = silu_f(p1.y + bb.w);
            *(float4*)&g_h[node * D + 4 * cg] = o;
        }
    }
}

// ---------------- node GEMM: [k'|qv-interleaved] -> g_kqv, skip+conv_bias -> g_agg -----
#define HP 130
__global__ __launch_bounds__(256, 2) void k_nodegemm(
    const float* __restrict__ Wk, const float* __restrict__ bk,
    const float* __restrict__ Wq, const float* __restrict__ bq,
    const float* __restrict__ Wv, const float* __restrict__ bv,
    const float* __restrict__ Wskip, const float* __restrict__ cbias, int l) {
    extern __shared__ float dsm[];
    float* wsm = dsm;               // [64][256]
    float* hst = dsm + 64 * 256;    // [64][HP] transposed h tile
    int t = threadIdx.x;
    const float* WK = Wk + l * D * D;
    const float* WQ = Wq + l * D * D;
    const float* WV = Wv + l * D * D;
    const float* WS = Wskip + l * D * D;
    const float* BK = bk + l * D;
    const float* BQ = bq + l * D;
    const float* BV = bv + l * D;
    const float* CB = cbias + l * D;

    for (int i = t; i < 64 * 256; i += 256) {
        int j = i >> 8, c = i & 255;
        float v;
        if (c < 64)       v = WK[j * 64 + c];
        else if (c < 128) v = WQ[j * 64 + c - 64];
        else if (c < 192) v = WV[j * 64 + c - 128];
        else              v = WS[j * 64 + c - 192];
        wsm[i] = v;
    }
    int nb = blockIdx.x * 128;
    for (int i = t; i < 128 * 64; i += 256) {
        int r = i >> 6, c = i & 63;
        int node = nb + r;
        hst[c * HP + r] = (node < N_NODES) ? g_h[node * D + c] : 0.f;
    }
    if (blockIdx.x == 0 && t < 2 * D) g_stats[t] = 0.f;  // zero BN stats for this layer
    __syncthreads();

    int cg = t & 31;
    int warp = t >> 5;
    int cA = 4 * cg;          // 0..124
    int cB = 128 + 4 * cg;    // 128..252
    float4 bA, bB;
    if (cA < 64) bA = make_float4(BK[cA] + BQ[cA], BK[cA + 1] + BQ[cA + 1],
                                  BK[cA + 2] + BQ[cA + 2], BK[cA + 3] + BQ[cA + 3]);
    else         bA = make_float4(0.f, 0.f, 0.f, 0.f);
    if (cB < 192) bB = make_float4(BV[cB - 128], BV[cB - 127], BV[cB - 126], BV[cB - 125]);
    else          bB = make_float4(CB[cB - 192], CB[cB - 191], CB[cB - 190], CB[cB - 189]);

    for (int pass = 0; pass < 2; ++pass) {
        int rowbase = pass * 64 + warp * 8;
        u64 accA[4][4], accB[4][4];   // [rowpair][col]
#pragma unroll
        for (int pp = 0; pp < 4; ++pp)
#pragma unroll
            for (int cc = 0; cc < 4; ++cc) { accA[pp][cc] = 0ull; accB[pp][cc] = 0ull; }
#pragma unroll 8
        for (int j = 0; j < 64; ++j) {
            float4 wA = *(const float4*)&wsm[j * 256 + cA];
            float4 wB = *(const float4*)&wsm[j * 256 + cB];
            u64 wa0 = dup2(wA.x), wa1 = dup2(wA.y), wa2 = dup2(wA.z), wa3 = dup2(wA.w);
            u64 wb0 = dup2(wB.x), wb1 = dup2(wB.y), wb2 = dup2(wB.z), wb3 = dup2(wB.w);
            const float* hj = &hst[j * HP + rowbase];
#pragma unroll
            for (int pp = 0; pp < 4; ++pp) {
                u64 h2 = *(const u64*)&hj[2 * pp];   // broadcast LDS.64 (rows 2pp,2pp+1)
                accA[pp][0] = ffma2(h2, wa0, accA[pp][0]);
                accA[pp][1] = ffma2(h2, wa1, accA[pp][1]);
                accA[pp][2] = ffma2(h2, wa2, accA[pp][2]);
                accA[pp][3] = ffma2(h2, wa3, accA[pp][3]);
                accB[pp][0] = ffma2(h2, wb0, accB[pp][0]);
                accB[pp][1] = ffma2(h2, wb1, accB[pp][1]);
                accB[pp][2] = ffma2(h2, wb2, accB[pp][2]);
                accB[pp][3] = ffma2(h2, wb3, accB[pp][3]);
            }
        }
#pragma unroll
        for (int pp = 0; pp < 4; ++pp) {
            float2 uA[4], uB[4];
#pragma unroll
            for (int cc = 0; cc < 4; ++cc) { uA[cc] = unpk(accA[pp][cc]); uB[cc] = unpk(accB[pp][cc]); }
#pragma unroll
            for (int s = 0; s < 2; ++s) {
                int node = nb + rowbase + 2 * pp + s;
                if (node >= N_NODES) continue;
                float a0 = (s ? uA[0].y : uA[0].x) + bA.x;
                float a1 = (s ? uA[1].y : uA[1].x) + bA.y;
                float a2 = (s ? uA[2].y : uA[2].x) + bA.z;
                float a3 = (s ? uA[3].y : uA[3].x) + bA.w;
                float b0 = (s ? uB[0].y : uB[0].x) + bB.x;
                float b1 = (s ? uB[1].y : uB[1].x) + bB.y;
                float b2 = (s ? uB[2].y : uB[2].x) + bB.z;
                float b3 = (s ? uB[3].y : uB[3].x) + bB.w;
                if (cA < 64) {
                    *(float4*)&g_kqv[node * 192 + cA] = make_float4(a0, a1, a2, a3);
                } else {
                    int q0 = cA - 64;   // multiple of 4
                    *(float2*)&g_kqv[node * 192 + 64 + 2 * q0]     = make_float2(a0, a1);
                    *(float2*)&g_kqv[node * 192 + 64 + 2 * q0 + 4] = make_float2(a2, a3);
                }
                if (cB < 192) {
                    int v0 = cB - 128;  // multiple of 4
                    *(float2*)&g_kqv[node * 192 + 64 + 2 * v0 + 2] = make_float2(b0, b1);
                    *(float2*)&g_kqv[node * 192 + 64 + 2 * v0 + 6] = make_float2(b2, b3);
                } else {
                    *(float4*)&g_agg[node * 64 + (cB - 192)] = make_float4(b0, b1, b2, b3);
                }
            }
        }
    }
}

// ---------------- edge kernel: fused e=attr@We + gate + scatter, 4 CTAs/SM -------------
// 1 edge/warp/iter. ALL staging via cp.async rings with L2 cache policies:
//   attr (320MB stream): evict_first — do NOT evict the kqv table;
//   kqv gathers (76MB working set): evict_last — pin in L2.
// attr: 4 bufs committed 3 iters ahead; kv: 4 bufs committed 2 ahead; wait_group 3.
__global__ __launch_bounds__(128, 4) void k_edge(const float* __restrict__ eattr,
                                                 const float* __restrict__ We, int l) {
    __shared__ __align__(16) float sa[4][4][52];     // [buf][warp][attr]
    __shared__ __align__(16) float skv[4][4][192];   // [warp][buf][ k:0..63 | qv:64..191 ]
    const int lane = threadIdx.x & 31;
    const int w = threadIdx.x >> 5;
    const float* WE = We + l * E_IN * D;
    u64 pol_stream, pol_keep;
    asm("createpolicy.fractional.L2::evict_first.b64 %0, 1.0;" : "=l"(pol_stream));
    asm("createpolicy.fractional.L2::evict_last.b64 %0, 1.0;" : "=l"(pol_keep));
    u64 wr[E_IN];
#pragma unroll
    for (int j = 0; j < E_IN; ++j) {
        float2 v = *(const float2*)&WE[j * D + 2 * lane];
        wr[j] = pack2(v.x, v.y);
    }
    const int gw = (blockIdx.x * blockDim.x + threadIdx.x) >> 5;
    const int nw = (gridDim.x * blockDim.x) >> 5;
    const bool al = (lane < 25);
#define CL(x) ((x) < N_EDGES ? (x) : (N_EDGES - 1))
    const uint32_t s_k  = (uint32_t)__cvta_generic_to_shared(&skv[w][0][2 * lane]);
    const uint32_t s_qv = (uint32_t)__cvta_generic_to_shared(&skv[w][0][64 + 4 * lane]);
    const uint32_t s_a  = (uint32_t)__cvta_generic_to_shared(&sa[0][w][2 * lane]);

    int e = gw;
    int2 pC = g_sd[CL(e)];
    int2 pN = g_sd[CL(e + nw)];
    int2 pNN = g_sd[CL(e + 2 * nw)];
    // prologue groups (order matters for wait_group 3 at iter0):
    // A0, K0(kv e), K1(kv e+nw), A1, A2
    if (al) cpa8_pol(s_a, &eattr[(size_t)CL(e) * E_IN + 2 * lane], pol_stream);
    asm volatile("cp.async.commit_group;");
    cpa8_pol(s_k, &g_kqv[pC.y * 192 + 2 * lane], pol_keep);
    cpa16_pol(s_qv, &g_kqv[pC.x * 192 + 64 + 4 * lane], pol_keep);
    asm volatile("cp.async.commit_group;");
    cpa8_pol(s_k + 192 * 4, &g_kqv[pN.y * 192 + 2 * lane], pol_keep);
    cpa16_pol(s_qv + 192 * 4, &g_kqv[pN.x * 192 + 64 + 4 * lane], pol_keep);
    asm volatile("cp.async.commit_group;");
    if (al) cpa8_pol(s_a + 4 * 52 * 4, &eattr[(size_t)CL(e + nw) * E_IN + 2 * lane], pol_stream);
    asm volatile("cp.async.commit_group;");
    if (al) cpa8_pol(s_a + 2 * 4 * 52 * 4, &eattr[(size_t)CL(e + 2 * nw) * E_IN + 2 * lane], pol_stream);
    asm volatile("cp.async.commit_group;");
    int cnt = 0;

    while (e < N_EDGES) {
        // depth-3 index prefetch
        int2 p3 = g_sd[CL(e + 3 * nw)];
        // kv(2-back) + attr(3-back) complete; syncwarp publishes cross-lane attr
        asm volatile("cp.async.wait_group 3;");
        __syncwarp();
        // commit kv for e+2nw (indices pNN, loaded last iteration)
        {
            uint32_t off = (uint32_t)(((cnt + 2) & 3) * 192 * 4);
            cpa8_pol(s_k + off, &g_kqv[pNN.y * 192 + 2 * lane], pol_keep);
            cpa16_pol(s_qv + off, &g_kqv[pNN.x * 192 + 64 + 4 * lane], pol_keep);
        }
        asm volatile("cp.async.commit_group;");
        // commit attr for e+3nw
        if (al) cpa8_pol(s_a + (uint32_t)(((cnt + 3) & 3) * 4 * 52 * 4),
                         &eattr[(size_t)CL(e + 3 * nw) * E_IN + 2 * lane], pol_stream);
        asm volatile("cp.async.commit_group;");
        // ---- FMA on attr buf cnt&3 (2 independent chains) ----
        const float* rowA = sa[cnt & 3][w];
        u64 a0 = 0ull, a1 = 0ull;
#pragma unroll
        for (int j = 0; j < 48; j += 4) {
            float4 a = *(const float4*)&rowA[j];
            a0 = ffma2(dup2(a.x), wr[j],     a0);
            a1 = ffma2(dup2(a.y), wr[j + 1], a1);
            a0 = ffma2(dup2(a.z), wr[j + 2], a0);
            a1 = ffma2(dup2(a.w), wr[j + 3], a1);
        }
        {
            float2 a = *(const float2*)&rowA[48];
            a0 = ffma2(dup2(a.x), wr[48], a0);
            a1 = ffma2(dup2(a.y), wr[49], a1);
        }
        float2 ev = unpk(addf2(a0, a1));
        // ---- gate + scatter (k/qv from smem buf cnt&3) ----
        {
            const float* kb = skv[w][cnt & 3];
            float2 kC = *(const float2*)&kb[2 * lane];
            float4 qv = *(const float4*)&kb[64 + 4 * lane];
            float x0 = kC.x + qv.x + 2.0f * ev.x;   // k' includes bk+bq
            float x1 = kC.y + qv.y + 2.0f * ev.y;
            float2 m;
            m.x = silu_f(x0) * (qv.z + ev.x);
            m.y = silu_f(x1) * (qv.w + ev.y);
            atomicAdd((float2*)&g_agg[pC.y * 64 + 2 * lane], m);
        }
        // rotate
        pC = pN; pN = pNN; pNN = p3;
        cnt = (cnt + 1) & 3;
        e += nw;
    }
#undef CL
}

// ---------------- BN stats: per-column sum & sumsq over nodes ----------------
__global__ __launch_bounds__(256) void k_bnstats() {
    int t = threadIdx.x;
    int col = t & 63;
    int rs = t >> 6;
    float s = 0.f, s2 = 0.f;
    for (int row = blockIdx.x * 4 + rs; row < N_NODES; row += gridDim.x * 4) {
        float v = g_agg[row * 64 + col];
        s += v; s2 += v * v;
    }
    __shared__ float sh[256], sh2[256];
    sh[t] = s; sh2[t] = s2;
    __syncthreads();
    if (rs == 0) {
        s = sh[col] + sh[col + 64] + sh[col + 128] + sh[col + 192];
        s2 = sh2[col] + sh2[col + 64] + sh2[col + 128] + sh2[col + 192];
        atomicAdd(&g_stats[col], s);
        atomicAdd(&g_stats[64 + col], s2);
    }
}

// ---------------- BN apply: h = (agg-mean)*rsqrt(var+eps)*gamma+beta; also zero pool bufs ---
__global__ __launch_bounds__(256) void k_bnapply(const float* __restrict__ gamma,
                                                 const float* __restrict__ beta, int l) {
    __shared__ float sc[64], sf[64];
    int t = threadIdx.x;
    if (t < 64) {
        const float invN = 1.0f / (float)N_NODES;
        float mean = g_stats[t] * invN;
        float var = g_stats[64 + t] * invN - mean * mean;
        float gm = gamma[l * 64 + t], bt = beta[l * 64 + t];
        float scale = gm * rsqrtf(var + BN_EPS);
        sc[t] = scale;
        sf[t] = bt - mean * scale;
    }
    __syncthreads();
    int gt = blockIdx.x * 256 + t;
    int stride = gridDim.x * 256;
    for (int i = gt; i < N_NODES * 64; i += stride) {
        int col = i & 63;
        g_h[i] = g_agg[i] * sc[col] + sf[col];
    }
    for (int i = gt; i < N_GRAPHS * 64; i += stride) g_gsum[i] = 0.f;
    for (int i = gt; i < N_GRAPHS; i += stride) g_gcnt[i] = 0.f;
}

// ---------------- global mean pool (sums + counts via atomics) ----------------
__global__ __launch_bounds__(256) void k_pool() {
    int t = threadIdx.x;
    int col = t & 63;
    int rs = t >> 6;
    for (int row = blockIdx.x * 4 + rs; row < N_NODES; row += gridDim.x * 4) {
        int b = g_bidx[row];
        atomicAdd(&g_gsum[b * 64 + col], g_h[row * 64 + col]);
        if (col == 0) atomicAdd(&g_gcnt[b], 1.f);
    }
}

// ---------------- final: g = silu(mean @ post_w + post_b); out = g @ out_w + out_b ------
__global__ __launch_bounds__(128) void k_final(const float* __restrict__ pw,
                                               const float* __restrict__ pb,
                                               const float* __restrict__ ow,
                                               const float* __restrict__ ob,
                                               float* __restrict__ out) {
    __shared__ float ws[64 * 64];
    __shared__ float sg[4][64];
    int t = threadIdx.x;
    for (int i = t; i < 4096; i += 128) ws[i] = pw[i];
    __syncthreads();
    int lane = t & 31, w = t >> 5;
    int g = blockIdx.x * 4 + w;
    if (g < N_GRAPHS) {
        float inv = 1.0f / fmaxf(g_gcnt[g], 1.0f);
        sg[w][lane] = g_gsum[g * 64 + lane] * inv;
        sg[w][lane + 32] = g_gsum[g * 64 + lane + 32] * inv;
    }
    __syncwarp();
    if (g < N_GRAPHS) {
        float a0 = pb[lane], a1 = pb[lane + 32];
#pragma unroll 8
        for (int j = 0; j < 64; ++j) {
            float xv = sg[w][j];
            a0 = fmaf(xv, ws[j * 64 + lane], a0);
            a1 = fmaf(xv, ws[j * 64 + lane + 32], a1);
        }
        float t0 = silu_f(a0), t1 = silu_f(a1);
        float p = t0 * ow[lane] + t1 * ow[lane + 32];
#pragma unroll
        for (int o = 16; o; o >>= 1) p += __shfl_down_sync(0xffffffffu, p, o);
        if (lane == 0) out[g] = p + ob[0];
    }
}

// ---------------- launch ----------------
extern "C" void kernel_launch(void* const* d_in, const int* in_sizes, int n_in,
                              void* d_out, int out_size) {
    const float* x     = (const float*)d_in[0];
    const void*  eidx  = d_in[1];
    const float* eattr = (const float*)d_in[2];
    const void*  bidx  = d_in[3];
    const float* pre_w = (const float*)d_in[4];
    const float* pre_b = (const float*)d_in[5];
    const float* Wk    = (const float*)d_in[6];
    const float* bk    = (const float*)d_in[7];
    const float* Wq    = (const float*)d_in[8];
    const float* bq    = (const float*)d_in[9];
    const float* Wv    = (const float*)d_in[10];
    const float* bv    = (const float*)d_in[11];
    const float* We    = (const float*)d_in[12];
    const float* Wskip = (const float*)d_in[13];
    const float* cbias = (const float*)d_in[14];
    const float* gamma = (const float*)d_in[15];
    const float* beta  = (const float*)d_in[16];
    const float* pw    = (const float*)d_in[17];
    const float* pb    = (const float*)d_in[18];
    const float* ow    = (const float*)d_in[19];
    const float* ob    = (const float*)d_in[20];
    float* out = (float*)d_out;
    (void)in_sizes; (void)n_in; (void)out_size;

    const int gemm_smem = (64 * 256 + 64 * HP) * (int)sizeof(float);  // 98816 B
    cudaFuncSetAttribute(k_nodegemm, cudaFuncAttributeMaxDynamicSharedMemorySize, gemm_smem);

    // Launch order keeps k_edge in the profiled (4th) slot.
    k_convert<<<256, 256>>>(eidx, bidx);
    k_prefc<<<(N_NODES + 63) / 64, 256>>>(x, pre_w, pre_b);
    for (int l = 0; l < N_LAYERS; ++l) {
        k_nodegemm<<<(N_NODES + 127) / 128, 256, gemm_smem>>>(Wk, bk, Wq, bq, Wv, bv,
                                                              Wskip, cbias, l);
        k_edge<<<592, 128>>>(eattr, We, l);
        k_bnstats<<<128, 256>>>();
        k_bnapply<<<512, 256>>>(gamma, beta, l);
    }
    k_pool<<<256, 256>>>();
    k_final<<<(N_GRAPHS + 3) / 4, 128>>>(pw, pb, ow, ob, out);
}

// round 15
// speedup vs baseline: 1.9445x; 1.1321x over previous
#include <cuda_runtime.h>
#include <cstdint>
#include <cstddef>

#define N_NODES 100000
#define N_EDGES 1600000
#define F_IN 92
#define E_IN 50
#define D 64
#define N_LAYERS 3
#define N_GRAPHS 512
#define BN_EPS 1e-5f

typedef unsigned long long u64;
typedef long long i64;

// ---------------- scratch (device globals; no runtime allocation) ----------------
// g_kqv layout per node (192 floats):
//   [0..63]   : k' = h@Wk + bk + bq                (used at dst)
//   [64..191] : interleaved qv: for col pair c (0..31):
//               [64+4c+0,1] = q[2c], q[2c+1]       (used at src)
//               [64+4c+2,3] = v[2c], v[2c+1] (+bv) (used at src)
__device__ float g_h[N_NODES * D];          // layer-0 input (pre-FC output)
__device__ float g_kqv[N_NODES * 3 * D];
__device__ float g_agg[N_NODES * D];        // init = h@Wskip + conv_bias, edges atomically add
__device__ float g_stats[N_LAYERS * 2 * D]; // per-layer BN col sums / sumsq (zeroed in convert)
__device__ float g_gsum[N_GRAPHS * D];      // pooling sums
__device__ float g_gcnt[N_GRAPHS];          // pooling counts
__device__ int2  g_sd[N_EDGES];             // packed (src,dst) int32 indices
__device__ int   g_bidx[N_NODES];

// ---------------- packed f32x2 helpers ----------------
__device__ __forceinline__ u64 pack2(float x, float y) {
    u64 r; asm("mov.b64 %0,{%1,%2};" : "=l"(r) : "f"(x), "f"(y)); return r;
}
__device__ __forceinline__ u64 dup2(float x) {
    u64 r; asm("mov.b64 %0,{%1,%1};" : "=l"(r) : "f"(x)); return r;
}
__device__ __forceinline__ float2 unpk(u64 v) {
    float2 o; asm("mov.b64 {%0,%1},%2;" : "=f"(o.x), "=f"(o.y) : "l"(v)); return o;
}
__device__ __forceinline__ u64 ffma2(u64 a, u64 b, u64 c) {
    u64 d; asm("fma.rn.f32x2 %0,%1,%2,%3;" : "=l"(d) : "l"(a), "l"(b), "l"(c)); return d;
}
__device__ __forceinline__ u64 addf2(u64 a, u64 b) {
    u64 d; asm("add.rn.f32x2 %0,%1,%2;" : "=l"(d) : "l"(a), "l"(b)); return d;
}
__device__ __forceinline__ float silu_f(float x) {
    return __fdividef(x, 1.0f + __expf(-x));
}
__device__ __forceinline__ void cpa8(uint32_t s, const void* g) {
    asm volatile("cp.async.ca.shared.global [%0], [%1], 8;" :: "r"(s), "l"(g));
}
__device__ __forceinline__ void cpa16(uint32_t s, const void* g) {
    asm volatile("cp.async.ca.shared.global [%0], [%1], 16;" :: "r"(s), "l"(g));
}

// ---------------- index normalize + zero all accumulators (one launch) -------------
__global__ __launch_bounds__(256) void k_convert(const void* __restrict__ eidx,
                                                 const void* __restrict__ bidx) {
    __shared__ int s64;
    if (threadIdx.x == 0) {
        const unsigned* w = (const unsigned*)eidx;
        int is64 = 1;
        for (int i = 1; i < 129; i += 2)
            if (w[i] != 0u) { is64 = 0; break; }
        s64 = is64;
    }
    __syncthreads();
    const int is64 = s64;
    int gt = blockIdx.x * 256 + threadIdx.x;
    int stride = gridDim.x * 256;
    if (is64) {
        const i64* e = (const i64*)eidx;
        const i64* b = (const i64*)bidx;
        for (int i = gt; i < N_EDGES; i += stride)
            g_sd[i] = make_int2((int)e[i], (int)e[N_EDGES + i]);
        for (int i = gt; i < N_NODES; i += stride) g_bidx[i] = (int)b[i];
    } else {
        const int* e = (const int*)eidx;
        const int* b = (const int*)bidx;
        for (int i = gt; i < N_EDGES; i += stride)
            g_sd[i] = make_int2(e[i], e[N_EDGES + i]);
        for (int i = gt; i < N_NODES; i += stride) g_bidx[i] = b[i];
    }
    for (int i = gt; i < N_LAYERS * 2 * D; i += stride) g_stats[i] = 0.f;
    for (int i = gt; i < N_GRAPHS * D; i += stride) g_gsum[i] = 0.f;
    for (int i = gt; i < N_GRAPHS; i += stride) g_gcnt[i] = 0.f;
}

// ---------------- pre-FC: h = silu(x @ pre_w + pre_b) ----------------
__global__ __launch_bounds__(256) void k_prefc(const float* __restrict__ x,
                                               const float* __restrict__ w,
                                               const float* __restrict__ b) {
    __shared__ float ws[F_IN * D];       // 23552 B
    __shared__ float xs[64 * F_IN];      // 23552 B
    int t = threadIdx.x;
    for (int i = t; i < F_IN * D; i += 256) ws[i] = w[i];
    int nb = blockIdx.x * 64;
    for (int i = t; i < 64 * F_IN; i += 256) {
        int r = i / F_IN, c = i - r * F_IN;
        int node = nb + r;
        xs[i] = (node < N_NODES) ? x[(size_t)node * F_IN + c] : 0.f;
    }
    __syncthreads();
    int cg = t & 15;
    int r0 = t >> 4;
    float4 bb = *(const float4*)&b[4 * cg];
    for (int pass = 0; pass < 4; ++pass) {
        int row = pass * 16 + r0;
        int node = nb + row;
        u64 a0 = 0ull, a1 = 0ull;
#pragma unroll 4
        for (int j = 0; j < F_IN; ++j) {
            u64 xv = dup2(xs[row * F_IN + j]);
            float4 wv = *(const float4*)&ws[j * D + 4 * cg];
            a0 = ffma2(xv, pack2(wv.x, wv.y), a0);
            a1 = ffma2(xv, pack2(wv.z, wv.w), a1);
        }
        if (node < N_NODES) {
            float2 p0 = unpk(a0), p1 = unpk(a1);
            float4 o;
            o.x = silu_f(p0.x + bb.x);
            o.y = silu_f(p0.y + bb.y);
            o.z = silu_f(p1.x + bb.z);
            o.w = silu_f(p1.y + bb.w);
            *(float4*)&g_h[node * D + 4 * cg] = o;
        }
    }
}

// ---------------- node GEMM with fused BN-apply on input ------------------------------
// layer 0: input = g_h. layer l>0: input = BN_{l-1}(g_agg) applied on-the-fly using
// g_stats[l-1] + gamma/beta[l-1] (bnapply kernel eliminated).
#define HP 130
__global__ __launch_bounds__(256, 2) void k_nodegemm(
    const float* __restrict__ Wk, const float* __restrict__ bk,
    const float* __restrict__ Wq, const float* __restrict__ bq,
    const float* __restrict__ Wv, const float* __restrict__ bv,
    const float* __restrict__ Wskip, const float* __restrict__ cbias,
    const float* __restrict__ gamma, const float* __restrict__ beta, int l) {
    extern __shared__ float dsm[];
    __shared__ float sbn[2 * D];    // [scale | shift]
    float* wsm = dsm;               // [64][256]
    float* hst = dsm + 64 * 256;    // [64][HP] transposed input tile
    int t = threadIdx.x;
    const float* WK = Wk + l * D * D;
    const float* WQ = Wq + l * D * D;
    const float* WV = Wv + l * D * D;
    const float* WS = Wskip + l * D * D;
    const float* BK = bk + l * D;
    const float* BQ = bq + l * D;
    const float* BV = bv + l * D;
    const float* CB = cbias + l * D;

    if (l > 0 && t < D) {
        const float invN = 1.0f / (float)N_NODES;
        const float* st = &g_stats[(l - 1) * 2 * D];
        float mean = st[t] * invN;
        float var = st[D + t] * invN - mean * mean;
        float scale = gamma[(l - 1) * D + t] * rsqrtf(var + BN_EPS);
        sbn[t] = scale;
        sbn[D + t] = beta[(l - 1) * D + t] - mean * scale;
    }
    for (int i = t; i < 64 * 256; i += 256) {
        int j = i >> 8, c = i & 255;
        float v;
        if (c < 64)       v = WK[j * 64 + c];
        else if (c < 128) v = WQ[j * 64 + c - 64];
        else if (c < 192) v = WV[j * 64 + c - 128];
        else              v = WS[j * 64 + c - 192];
        wsm[i] = v;
    }
    __syncthreads();   // sbn ready before hst load
    int nb = blockIdx.x * 128;
    if (l == 0) {
        for (int i = t; i < 128 * 64; i += 256) {
            int r = i >> 6, c = i & 63;
            int node = nb + r;
            hst[c * HP + r] = (node < N_NODES) ? g_h[node * D + c] : 0.f;
        }
    } else {
        for (int i = t; i < 128 * 64; i += 256) {
            int r = i >> 6, c = i & 63;
            int node = nb + r;
            hst[c * HP + r] = (node < N_NODES)
                ? g_agg[node * D + c] * sbn[c] + sbn[D + c] : 0.f;
        }
    }
    __syncthreads();

    int cg = t & 31;
    int warp = t >> 5;
    int cA = 4 * cg;          // 0..124
    int cB = 128 + 4 * cg;    // 128..252
    float4 bA, bB;
    if (cA < 64) bA = make_float4(BK[cA] + BQ[cA], BK[cA + 1] + BQ[cA + 1],
                                  BK[cA + 2] + BQ[cA + 2], BK[cA + 3] + BQ[cA + 3]);
    else         bA = make_float4(0.f, 0.f, 0.f, 0.f);
    if (cB < 192) bB = make_float4(BV[cB - 128], BV[cB - 127], BV[cB - 126], BV[cB - 125]);
    else          bB = make_float4(CB[cB - 192], CB[cB - 191], CB[cB - 190], CB[cB - 189]);

    for (int pass = 0; pass < 2; ++pass) {
        int rowbase = pass * 64 + warp * 8;
        u64 accA[4][4], accB[4][4];   // [rowpair][col]
#pragma unroll
        for (int pp = 0; pp < 4; ++pp)
#pragma unroll
            for (int cc = 0; cc < 4; ++cc) { accA[pp][cc] = 0ull; accB[pp][cc] = 0ull; }
#pragma unroll 8
        for (int j = 0; j < 64; ++j) {
            float4 wA = *(const float4*)&wsm[j * 256 + cA];
            float4 wB = *(const float4*)&wsm[j * 256 + cB];
            u64 wa0 = dup2(wA.x), wa1 = dup2(wA.y), wa2 = dup2(wA.z), wa3 = dup2(wA.w);
            u64 wb0 = dup2(wB.x), wb1 = dup2(wB.y), wb2 = dup2(wB.z), wb3 = dup2(wB.w);
            const float* hj = &hst[j * HP + rowbase];
#pragma unroll
            for (int pp = 0; pp < 4; ++pp) {
                u64 h2 = *(const u64*)&hj[2 * pp];   // broadcast LDS.64 (rows 2pp,2pp+1)
                accA[pp][0] = ffma2(h2, wa0, accA[pp][0]);
                accA[pp][1] = ffma2(h2, wa1, accA[pp][1]);
                accA[pp][2] = ffma2(h2, wa2, accA[pp][2]);
                accA[pp][3] = ffma2(h2, wa3, accA[pp][3]);
                accB[pp][0] = ffma2(h2, wb0, accB[pp][0]);
                accB[pp][1] = ffma2(h2, wb1, accB[pp][1]);
                accB[pp][2] = ffma2(h2, wb2, accB[pp][2]);
                accB[pp][3] = ffma2(h2, wb3, accB[pp][3]);
            }
        }
#pragma unroll
        for (int pp = 0; pp < 4; ++pp) {
            float2 uA[4], uB[4];
#pragma unroll
            for (int cc = 0; cc < 4; ++cc) { uA[cc] = unpk(accA[pp][cc]); uB[cc] = unpk(accB[pp][cc]); }
#pragma unroll
            for (int s = 0; s < 2; ++s) {
                int node = nb + rowbase + 2 * pp + s;
                if (node >= N_NODES) continue;
                float a0 = (s ? uA[0].y : uA[0].x) + bA.x;
                float a1 = (s ? uA[1].y : uA[1].x) + bA.y;
                float a2 = (s ? uA[2].y : uA[2].x) + bA.z;
                float a3 = (s ? uA[3].y : uA[3].x) + bA.w;
                float b0 = (s ? uB[0].y : uB[0].x) + bB.x;
                float b1 = (s ? uB[1].y : uB[1].x) + bB.y;
                float b2 = (s ? uB[2].y : uB[2].x) + bB.z;
                float b3 = (s ? uB[3].y : uB[3].x) + bB.w;
                if (cA < 64) {
                    *(float4*)&g_kqv[node * 192 + cA] = make_float4(a0, a1, a2, a3);
                } else {
                    int q0 = cA - 64;   // multiple of 4
                    *(float2*)&g_kqv[node * 192 + 64 + 2 * q0]     = make_float2(a0, a1);
                    *(float2*)&g_kqv[node * 192 + 64 + 2 * q0 + 4] = make_float2(a2, a3);
                }
                if (cB < 192) {
                    int v0 = cB - 128;  // multiple of 4
                    *(float2*)&g_kqv[node * 192 + 64 + 2 * v0 + 2] = make_float2(b0, b1);
                    *(float2*)&g_kqv[node * 192 + 64 + 2 * v0 + 6] = make_float2(b2, b3);
                } else {
                    *(float4*)&g_agg[node * 64 + (cB - 192)] = make_float4(b0, b1, b2, b3);
                }
            }
        }
    }
}

// ---------------- edge kernel: fused e=attr@We + gate + scatter, 4 CTAs/SM -------------
// 1 edge/warp/iter. ALL staging via cp.async rings (verified R12 config):
//   attr: 4 bufs, committed 3 iters ahead;  k/qv gathers: 4 bufs, committed 2 ahead.
// Per iter commits [kv][attr]; wait_group 3 forces kv(2-back) + attr(3-back) complete.
__global__ __launch_bounds__(128, 4) void k_edge(const float* __restrict__ eattr,
                                                 const float* __restrict__ We, int l) {
    __shared__ __align__(16) float sa[4][4][52];     // [buf][warp][attr]
    __shared__ __align__(16) float skv[4][4][192];   // [warp][buf][ k:0..63 | qv:64..191 ]
    const int lane = threadIdx.x & 31;
    const int w = threadIdx.x >> 5;
    const float* WE = We + l * E_IN * D;
    u64 wr[E_IN];
#pragma unroll
    for (int j = 0; j < E_IN; ++j) {
        float2 v = *(const float2*)&WE[j * D + 2 * lane];
        wr[j] = pack2(v.x, v.y);
    }
    const int gw = (blockIdx.x * blockDim.x + threadIdx.x) >> 5;
    const int nw = (gridDim.x * blockDim.x) >> 5;
    const bool al = (lane < 25);
#define CL(x) ((x) < N_EDGES ? (x) : (N_EDGES - 1))
    const uint32_t s_k  = (uint32_t)__cvta_generic_to_shared(&skv[w][0][2 * lane]);
    const uint32_t s_qv = (uint32_t)__cvta_generic_to_shared(&skv[w][0][64 + 4 * lane]);
    const uint32_t s_a  = (uint32_t)__cvta_generic_to_shared(&sa[0][w][2 * lane]);

    int e = gw;
    int2 pC = g_sd[CL(e)];
    int2 pN = g_sd[CL(e + nw)];
    int2 pNN = g_sd[CL(e + 2 * nw)];
    // prologue groups (order matters for wait_group 3 at iter0):
    // A0, K0(kv e), K1(kv e+nw), A1, A2
    if (al) cpa8(s_a, &eattr[(size_t)CL(e) * E_IN + 2 * lane]);
    asm volatile("cp.async.commit_group;");
    cpa8(s_k, &g_kqv[pC.y * 192 + 2 * lane]);
    cpa16(s_qv, &g_kqv[pC.x * 192 + 64 + 4 * lane]);
    asm volatile("cp.async.commit_group;");
    cpa8(s_k + 192 * 4, &g_kqv[pN.y * 192 + 2 * lane]);
    cpa16(s_qv + 192 * 4, &g_kqv[pN.x * 192 + 64 + 4 * lane]);
    asm volatile("cp.async.commit_group;");
    if (al) cpa8(s_a + 4 * 52 * 4, &eattr[(size_t)CL(e + nw) * E_IN + 2 * lane]);
    asm volatile("cp.async.commit_group;");
    if (al) cpa8(s_a + 2 * 4 * 52 * 4, &eattr[(size_t)CL(e + 2 * nw) * E_IN + 2 * lane]);
    asm volatile("cp.async.commit_group;");
    int cnt = 0;

    while (e < N_EDGES) {
        // depth-3 index prefetch
        int2 p3 = g_sd[CL(e + 3 * nw)];
        // kv(2-back) + attr(3-back) complete; syncwarp publishes cross-lane attr
        asm volatile("cp.async.wait_group 3;");
        __syncwarp();
        // commit kv for e+2nw (indices pNN, loaded last iteration)
        {
            uint32_t off = (uint32_t)(((cnt + 2) & 3) * 192 * 4);
            cpa8(s_k + off, &g_kqv[pNN.y * 192 + 2 * lane]);
            cpa16(s_qv + off, &g_kqv[pNN.x * 192 + 64 + 4 * lane]);
        }
        asm volatile("cp.async.commit_group;");
        // commit attr for e+3nw
        if (al) cpa8(s_a + (uint32_t)(((cnt + 3) & 3) * 4 * 52 * 4),
                     &eattr[(size_t)CL(e + 3 * nw) * E_IN + 2 * lane]);
        asm volatile("cp.async.commit_group;");
        // ---- FMA on attr buf cnt&3 (2 independent chains) ----
        const float* rowA = sa[cnt & 3][w];
        u64 a0 = 0ull, a1 = 0ull;
#pragma unroll
        for (int j = 0; j < 48; j += 4) {
            float4 a = *(const float4*)&rowA[j];
            a0 = ffma2(dup2(a.x), wr[j],     a0);
            a1 = ffma2(dup2(a.y), wr[j + 1], a1);
            a0 = ffma2(dup2(a.z), wr[j + 2], a0);
            a1 = ffma2(dup2(a.w), wr[j + 3], a1);
        }
        {
            float2 a = *(const float2*)&rowA[48];
            a0 = ffma2(dup2(a.x), wr[48], a0);
            a1 = ffma2(dup2(a.y), wr[49], a1);
        }
        float2 ev = unpk(addf2(a0, a1));
        // ---- gate + scatter (k/qv from smem buf cnt&3) ----
        {
            const float* kb = skv[w][cnt & 3];
            float2 kC = *(const float2*)&kb[2 * lane];
            float4 qv = *(const float4*)&kb[64 + 4 * lane];
            float x0 = kC.x + qv.x + 2.0f * ev.x;   // k' includes bk+bq
            float x1 = kC.y + qv.y + 2.0f * ev.y;
            float2 m;
            m.x = silu_f(x0) * (qv.z + ev.x);
            m.y = silu_f(x1) * (qv.w + ev.y);
            atomicAdd((float2*)&g_agg[pC.y * 64 + 2 * lane], m);
        }
        // rotate
        pC = pN; pN = pNN; pNN = p3;
        cnt = (cnt + 1) & 3;
        e += nw;
    }
#undef CL
}

// ---------------- BN stats: per-column sum & sumsq over nodes (per-layer buffer) -------
__global__ __launch_bounds__(256) void k_bnstats(int l) {
    int t = threadIdx.x;
    int col = t & 63;
    int rs = t >> 6;
    float s = 0.f, s2 = 0.f;
    for (int row = blockIdx.x * 4 + rs; row < N_NODES; row += gridDim.x * 4) {
        float v = g_agg[row * 64 + col];
        s += v; s2 += v * v;
    }
    __shared__ float sh[256], sh2[256];
    sh[t] = s; sh2[t] = s2;
    __syncthreads();
    if (rs == 0) {
        s = sh[col] + sh[col + 64] + sh[col + 128] + sh[col + 192];
        s2 = sh2[col] + sh2[col + 64] + sh2[col + 128] + sh2[col + 192];
        atomicAdd(&g_stats[l * 2 * D + col], s);
        atomicAdd(&g_stats[l * 2 * D + D + col], s2);
    }
}

// ---------------- global mean pool with fused BN-apply of the LAST layer ---------------
__global__ __launch_bounds__(256) void k_pool(const float* __restrict__ gamma,
                                              const float* __restrict__ beta) {
    __shared__ float sc[D], sf[D];
    int t = threadIdx.x;
    if (t < D) {
        const float invN = 1.0f / (float)N_NODES;
        const float* st = &g_stats[(N_LAYERS - 1) * 2 * D];
        float mean = st[t] * invN;
        float var = st[D + t] * invN - mean * mean;
        float scale = gamma[(N_LAYERS - 1) * D + t] * rsqrtf(var + BN_EPS);
        sc[t] = scale;
        sf[t] = beta[(N_LAYERS - 1) * D + t] - mean * scale;
    }
    __syncthreads();
    int col = t & 63;
    int rs = t >> 6;
    for (int row = blockIdx.x * 4 + rs; row < N_NODES; row += gridDim.x * 4) {
        int b = g_bidx[row];
        float hv = g_agg[row * 64 + col] * sc[col] + sf[col];
        atomicAdd(&g_gsum[b * 64 + col], hv);
        if (col == 0) atomicAdd(&g_gcnt[b], 1.f);
    }
}

// ---------------- final: g = silu(mean @ post_w + post_b); out = g @ out_w + out_b ------
__global__ __launch_bounds__(128) void k_final(const float* __restrict__ pw,
                                               const float* __restrict__ pb,
                                               const float* __restrict__ ow,
                                               const float* __restrict__ ob,
                                               float* __restrict__ out) {
    __shared__ float ws[64 * 64];
    __shared__ float sg[4][64];
    int t = threadIdx.x;
    for (int i = t; i < 4096; i += 128) ws[i] = pw[i];
    __syncthreads();
    int lane = t & 31, w = t >> 5;
    int g = blockIdx.x * 4 + w;
    if (g < N_GRAPHS) {
        float inv = 1.0f / fmaxf(g_gcnt[g], 1.0f);
        sg[w][lane] = g_gsum[g * 64 + lane] * inv;
        sg[w][lane + 32] = g_gsum[g * 64 + lane + 32] * inv;
    }
    __syncwarp();
    if (g < N_GRAPHS) {
        float a0 = pb[lane], a1 = pb[lane + 32];
#pragma unroll 8
        for (int j = 0; j < 64; ++j) {
            float xv = sg[w][j];
            a0 = fmaf(xv, ws[j * 64 + lane], a0);
            a1 = fmaf(xv, ws[j * 64 + lane + 32], a1);
        }
        float t0 = silu_f(a0), t1 = silu_f(a1);
        float p = t0 * ow[lane] + t1 * ow[lane + 32];
#pragma unroll
        for (int o = 16; o; o >>= 1) p += __shfl_down_sync(0xffffffffu, p, o);
        if (lane == 0) out[g] = p + ob[0];
    }
}

// ---------------- launch ----------------
extern "C" void kernel_launch(void* const* d_in, const int* in_sizes, int n_in,
                              void* d_out, int out_size) {
    const float* x     = (const float*)d_in[0];
    const void*  eidx  = d_in[1];
    const float* eattr = (const float*)d_in[2];
    const void*  bidx  = d_in[3];
    const float* pre_w = (const float*)d_in[4];
    const float* pre_b = (const float*)d_in[5];
    const float* Wk    = (const float*)d_in[6];
    const float* bk    = (const float*)d_in[7];
    const float* Wq    = (const float*)d_in[8];
    const float* bq    = (const float*)d_in[9];
    const float* Wv    = (const float*)d_in[10];
    const float* bv    = (const float*)d_in[11];
    const float* We    = (const float*)d_in[12];
    const float* Wskip = (const float*)d_in[13];
    const float* cbias = (const float*)d_in[14];
    const float* gamma = (const float*)d_in[15];
    const float* beta  = (const float*)d_in[16];
    const float* pw    = (const float*)d_in[17];
    const float* pb    = (const float*)d_in[18];
    const float* ow    = (const float*)d_in[19];
    const float* ob    = (const float*)d_in[20];
    float* out = (float*)d_out;
    (void)in_sizes; (void)n_in; (void)out_size;

    const int gemm_smem = (64 * 256 + 64 * HP) * (int)sizeof(float);  // 98816 B
    cudaFuncSetAttribute(k_nodegemm, cudaFuncAttributeMaxDynamicSharedMemorySize, gemm_smem);

    // Launch order keeps k_edge in the profiled (4th) slot.
    k_convert<<<256, 256>>>(eidx, bidx);
    k_prefc<<<(N_NODES + 63) / 64, 256>>>(x, pre_w, pre_b);
    for (int l = 0; l < N_LAYERS; ++l) {
        k_nodegemm<<<(N_NODES + 127) / 128, 256, gemm_smem>>>(Wk, bk, Wq, bq, Wv, bv,
                                                              Wskip, cbias, gamma, beta, l);
        k_edge<<<592, 128>>>(eattr, We, l);
        k_bnstats<<<512, 256>>>(l);
    }
    k_pool<<<256, 256>>>(gamma, beta);
    k_final<<<(N_GRAPHS + 3) / 4, 128>>>(pw, pb, ow, ob, out);
}